// round 5
// baseline (speedup 1.0000x reference)
#include <cuda_runtime.h>
#include <math.h>

#define NSEG    2047
#define NPIX    16384
#define GAMMA_F 200.0f
#define STEPF   (2.0f / 127.0f)
// tile = 8x4 px, center at (+3.5, +1.5): 2 * half-diagonal = 2*sqrt(3.5^2+1.5^2) px
#define THR_ADD (7.615773f * STEPF + 1e-3f)
#define FINF    __int_as_float(0x7F800000)

__device__ __forceinline__ float satmul(float a, float b) {
    float r; asm("mul.rn.sat.f32 %0,%1,%2;" : "=f"(r) : "f"(a), "f"(b)); return r;
}

__device__ float    g_partial[512];
__device__ unsigned g_count = 0;   // reset to 0 by the last CTA every run

// ---------------------------------------------------------------------------
// ONE kernel. grid = 512 CTAs (16 x-tiles of 8px, 32 y-tiles of 4px), 128 thr.
// Per CTA, for each transform w:
//   conv:   all 2047 segments -> smem SoA (masked -> pj=1e9, inv=0 => d2~2e18,
//           exp -> 0 exactly, matching betas*keep)
//   phase1: eval d2 at tile center (16 segs/thread), block-min U,
//           cull: keep d2(center) < (sqrt(U)+2r+eps)^2  [exact, triangle ineq]
//   phase2: thread = (pixel p=tid&31, slice h=tid>>5); each pixel's min over
//           the candidate list, 4 slices x 2 accumulator chains
// Then: merge slices, beta=exp(-gamma*d2) both w, squared diff, block sum,
// last-CTA global reduction writes out[0] directly (no zero/reduce kernels).
// ---------------------------------------------------------------------------
__global__ void __launch_bounds__(128) fused_kernel(const float* __restrict__ pred,
                                                    const float* __restrict__ gt,
                                                    float* __restrict__ out) {
    const int tid = threadIdx.x;
    const int bid = blockIdx.x;
    const int tx = bid & 15, ty = bid >> 4;

    const float cx = fmaf((float)(tx * 8) + 3.5f, STEPF, -1.0f);
    const float cy = fmaf((float)(ty * 4) + 1.5f, STEPF, -1.0f);

    const int p = tid & 31, h = tid >> 5;      // pixel, slice(=warp)
    const int col = p & 7, row = p >> 3;
    const float gx = fmaf((float)(tx * 8 + col), STEPF, -1.0f);
    const float gy = fmaf((float)(ty * 4 + row), STEPF, -1.0f);

    __shared__ float4 s_seg[2048];             // 32 KB
    __shared__ float  s_inv[2048];             //  8 KB
    __shared__ unsigned short s_list[2048];    //  4 KB
    __shared__ float  s_m[2][32][4];
    __shared__ float  s_red[4];
    __shared__ int    s_cnt;
    __shared__ bool   s_last;

    for (int w = 0; w < 2; ++w) {
        if (tid == 0) s_cnt = 0;
        const float* __restrict__ c = w ? gt : pred;

        // ---- convert segments into smem ----
#pragma unroll
        for (int k = 0; k < 16; ++k) {
            const int s = tid + (k << 7);
            float4 q = make_float4(1e9f, 1e9f, 0.0f, 0.0f);
            float inv = 0.0f;
            if (s < NSEG) {
                const float pen = __ldg(&c[s * 3 + 2]);
                const bool masked = w ? (pen != 0.0f) : (pen > 0.5f);
                if (!masked) {
                    const float pjx = fmaf(__ldg(&c[s * 3 + 3]), 2.0f, -1.0f);
                    const float pjy = fmaf(__ldg(&c[s * 3 + 4]), 2.0f, -1.0f);
                    const float vx  = fmaf(__ldg(&c[s * 3 + 0]), 2.0f, -1.0f) - pjx;
                    const float vy  = fmaf(__ldg(&c[s * 3 + 1]), 2.0f, -1.0f) - pjy;
                    const float vn  = vx * vx + vy * vy;
                    q = make_float4(pjx, pjy, vx, vy);
                    inv = (vn == 0.0f) ? 0.0f : (1.0f / vn);
                }
            }
            s_seg[s] = q;
            s_inv[s] = inv;
        }
        __syncthreads();

        // ---- phase 1: center eval + cull ----
        float d2c[16];
        float lmin = FINF;
#pragma unroll
        for (int k = 0; k < 16; ++k) {
            const int s = tid + (k << 7);
            const float4 q  = s_seg[s];
            const float inv = s_inv[s];
            const float ux = cx - q.x, uy = cy - q.y;
            const float uv = fmaf(ux, q.z, uy * q.w);
            const float t  = satmul(uv, inv);
            const float dx = fmaf(-t, q.z, ux);
            const float dy = fmaf(-t, q.w, uy);
            const float d2 = fmaf(dy, dy, dx * dx);
            d2c[k] = d2;
            lmin = fminf(lmin, d2);
        }
#pragma unroll
        for (int o = 16; o > 0; o >>= 1)
            lmin = fminf(lmin, __shfl_xor_sync(0xFFFFFFFFu, lmin, o));
        if ((tid & 31) == 0) s_red[tid >> 5] = lmin;
        __syncthreads();
        const float U   = fminf(fminf(s_red[0], s_red[1]), fminf(s_red[2], s_red[3]));
        const float thd = sqrtf(U) + THR_ADD;
        const float thr = thd * thd;
#pragma unroll
        for (int k = 0; k < 16; ++k) {
            if (d2c[k] < thr) {
                const int pos = atomicAdd(&s_cnt, 1);
                s_list[pos] = (unsigned short)(tid + (k << 7));
            }
        }
        __syncthreads();

        // ---- phase 2: per-pixel min over candidates (broadcast LDS) ----
        const int len = s_cnt;
        float m0 = FINF, m1 = FINF;
        int j = h;
        for (; j + 4 < len; j += 8) {
            {
                const int s = s_list[j];
                const float4 q = s_seg[s]; const float inv = s_inv[s];
                const float ux = gx - q.x, uy = gy - q.y;
                const float uv = fmaf(ux, q.z, uy * q.w);
                const float t  = satmul(uv, inv);
                const float dx = fmaf(-t, q.z, ux);
                const float dy = fmaf(-t, q.w, uy);
                m0 = fminf(m0, fmaf(dy, dy, dx * dx));
            }
            {
                const int s = s_list[j + 4];
                const float4 q = s_seg[s]; const float inv = s_inv[s];
                const float ux = gx - q.x, uy = gy - q.y;
                const float uv = fmaf(ux, q.z, uy * q.w);
                const float t  = satmul(uv, inv);
                const float dx = fmaf(-t, q.z, ux);
                const float dy = fmaf(-t, q.w, uy);
                m1 = fminf(m1, fmaf(dy, dy, dx * dx));
            }
        }
        for (; j < len; j += 4) {
            const int s = s_list[j];
            const float4 q = s_seg[s]; const float inv = s_inv[s];
            const float ux = gx - q.x, uy = gy - q.y;
            const float uv = fmaf(ux, q.z, uy * q.w);
            const float t  = satmul(uv, inv);
            const float dx = fmaf(-t, q.z, ux);
            const float dy = fmaf(-t, q.w, uy);
            m0 = fminf(m0, fmaf(dy, dy, dx * dx));
        }
        s_m[w][p][h] = fminf(m0, m1);
        __syncthreads();   // also protects s_seg/s_cnt reuse next iteration
    }

    // ---- loss for this tile's 32 pixels (warp 0) ----
    float v = 0.0f;
    if (tid < 32) {
        const float q0 = fminf(fminf(s_m[0][p][0], s_m[0][p][1]),
                               fminf(s_m[0][p][2], s_m[0][p][3]));
        const float q1 = fminf(fminf(s_m[1][p][0], s_m[1][p][1]),
                               fminf(s_m[1][p][2], s_m[1][p][3]));
        const float bp = expf(-GAMMA_F * q0);
        const float bg = expf(-GAMMA_F * q1);
        const float d  = bp - bg;
        v = d * d;
#pragma unroll
        for (int o = 16; o > 0; o >>= 1)
            v += __shfl_xor_sync(0xFFFFFFFFu, v, o);
        if (tid == 0) {
            g_partial[bid] = v;
            __threadfence();
            const unsigned t = atomicAdd(&g_count, 1u);
            s_last = (t == 511u);
        }
    }
    __syncthreads();

    // ---- last CTA: final reduction, direct store, counter reset ----
    if (s_last) {
        const volatile float* gp = g_partial;
        float acc = gp[tid] + gp[tid + 128] + gp[tid + 256] + gp[tid + 384];
#pragma unroll
        for (int o = 16; o > 0; o >>= 1)
            acc += __shfl_xor_sync(0xFFFFFFFFu, acc, o);
        if ((tid & 31) == 0) s_red[tid >> 5] = acc;
        __syncthreads();
        if (tid == 0) {
            out[0] = (s_red[0] + s_red[1] + s_red[2] + s_red[3]) * (1.0f / (float)NPIX);
            g_count = 0;
        }
    }
}

// ---------------------------------------------------------------------------
extern "C" void kernel_launch(void* const* d_in, const int* in_sizes, int n_in,
                              void* d_out, int out_size) {
    const float* pred = (const float*)d_in[0];
    const float* gt   = (const float*)d_in[1];
    float* out = (float*)d_out;

    fused_kernel<<<512, 128>>>(pred, gt, out);
}

// round 6
// speedup vs baseline: 1.4163x; 1.4163x over previous
#include <cuda_runtime.h>
#include <math.h>

#define NSEG    2047
#define NPIX    16384
#define NTILE   512          // 16 x-tiles (8px) * 32 y-tiles (4px)
#define GAMMA_F 200.0f
#define STEPF   (2.0f / 127.0f)
// tile = 8x4 px, center (+3.5,+1.5): 2*half-diag = 2*sqrt(3.5^2+1.5^2) px
#define THR_ADD (7.615773f * STEPF + 1e-3f)
#define FINF    __int_as_float(0x7F800000)

__device__ __forceinline__ float satmul(float a, float b) {
    float r; asm("mul.rn.sat.f32 %0,%1,%2;" : "=f"(r) : "f"(a), "f"(b)); return r;
}

// Cross-CTA state. All reset by the last loss-CTA each run (graph-replay safe).
__device__ float    g_pix[2][NPIX];     // per-pixel min d^2 (written every run)
__device__ int      g_tile_cnt[NTILE];  // 0 -> 1 -> 2 per tile per run
__device__ float    g_loss = 0.0f;
__device__ unsigned g_done = 0;

// ---------------------------------------------------------------------------
// ONE kernel, grid 1024 x 128: bid = w*512 + tile.
// Phase 1: 16 segs/thread, convert raw coords in-register, eval at tile
//          center, block-min U, cull via exact triangle-inequality bound.
// Phase 2: candidates staged (converted) into smem chunks; thread =
//          (pixel p = tid&31, slice h = tid>>5); 2 accumulator chains.
// Pairing: write 32 mins to g_pix[w]; second CTA of the tile computes the
//          tile's loss partial; 512th loss-CTA writes out[0] and resets.
// ---------------------------------------------------------------------------
__global__ void __launch_bounds__(128) fused_kernel(const float* __restrict__ pred,
                                                    const float* __restrict__ gt,
                                                    float* __restrict__ out) {
    const int tid  = threadIdx.x;
    const int bid  = blockIdx.x;
    const int w    = bid >> 9;
    const int tile = bid & (NTILE - 1);
    const int tx = tile & 15, ty = tile >> 4;

    const float* __restrict__ c = w ? gt : pred;

    const float cx = fmaf((float)(tx * 8) + 3.5f, STEPF, -1.0f);
    const float cy = fmaf((float)(ty * 4) + 1.5f, STEPF, -1.0f);

    const int p = tid & 31, h = tid >> 5;
    const int col = p & 7, row = p >> 3;
    const float gx = fmaf((float)(tx * 8 + col), STEPF, -1.0f);
    const float gy = fmaf((float)(ty * 4 + row), STEPF, -1.0f);

    __shared__ unsigned short s_list[2048];
    __shared__ float4 s_seg[256];
    __shared__ float  s_inv[256];
    __shared__ float  s_m[32][4];
    __shared__ float  s_red[4];
    __shared__ int    s_cnt;
    __shared__ int    s_flag;   // phase-ordering flags (second / last)

    if (tid == 0) s_cnt = 0;

    // ---------------- Phase 1: center eval + cull (raw input) ----------------
    float d2c[16];
    float lmin = FINF;
#pragma unroll
    for (int k = 0; k < 16; ++k) {
        const int s = tid + (k << 7);
        float d2 = FINF;
        if (s < NSEG) {
            const float pen = __ldg(&c[s * 3 + 2]);
            const bool masked = w ? (pen != 0.0f) : (pen > 0.5f);
            float pjx = fmaf(__ldg(&c[s * 3 + 3]), 2.0f, -1.0f);
            float pjy = fmaf(__ldg(&c[s * 3 + 4]), 2.0f, -1.0f);
            float vx  = fmaf(__ldg(&c[s * 3 + 0]), 2.0f, -1.0f) - pjx;
            float vy  = fmaf(__ldg(&c[s * 3 + 1]), 2.0f, -1.0f) - pjy;
            const float vn = vx * vx + vy * vy;
            float inv = (vn == 0.0f) ? 0.0f : (1.0f / vn);
            if (masked) { pjx = 1e9f; pjy = 1e9f; vx = 0.0f; vy = 0.0f; inv = 0.0f; }
            const float ux = cx - pjx, uy = cy - pjy;
            const float uv = fmaf(ux, vx, uy * vy);
            const float t  = satmul(uv, inv);
            const float dx = fmaf(-t, vx, ux);
            const float dy = fmaf(-t, vy, uy);
            d2 = fmaf(dy, dy, dx * dx);
        }
        d2c[k] = d2;
        lmin = fminf(lmin, d2);
    }
#pragma unroll
    for (int o = 16; o > 0; o >>= 1)
        lmin = fminf(lmin, __shfl_xor_sync(0xFFFFFFFFu, lmin, o));
    if ((tid & 31) == 0) s_red[tid >> 5] = lmin;
    __syncthreads();
    const float U   = fminf(fminf(s_red[0], s_red[1]), fminf(s_red[2], s_red[3]));
    const float thd = sqrtf(U) + THR_ADD;
    const float thr = thd * thd;
#pragma unroll
    for (int k = 0; k < 16; ++k) {
        if (d2c[k] < thr) {
            const int pos = atomicAdd(&s_cnt, 1);
            s_list[pos] = (unsigned short)(tid + (k << 7));
        }
    }
    __syncthreads();

    // ---------------- Phase 2: per-pixel min over candidates ----------------
    const int len = s_cnt;
    float m0 = FINF, m1 = FINF;
    for (int off = 0; off < len; off += 256) {
        const int cn = min(256, len - off);
        for (int j = tid; j < cn; j += 128) {
            const int s = s_list[off + j];
            const float pjx = fmaf(__ldg(&c[s * 3 + 3]), 2.0f, -1.0f);
            const float pjy = fmaf(__ldg(&c[s * 3 + 4]), 2.0f, -1.0f);
            const float vx  = fmaf(__ldg(&c[s * 3 + 0]), 2.0f, -1.0f) - pjx;
            const float vy  = fmaf(__ldg(&c[s * 3 + 1]), 2.0f, -1.0f) - pjy;
            const float vn  = vx * vx + vy * vy;
            s_seg[j] = make_float4(pjx, pjy, vx, vy);
            s_inv[j] = (vn == 0.0f) ? 0.0f : (1.0f / vn);
        }
        __syncthreads();
        int j = h;
        for (; j + 4 < cn; j += 8) {
            {
                const float4 q = s_seg[j]; const float inv = s_inv[j];
                const float ux = gx - q.x, uy = gy - q.y;
                const float uv = fmaf(ux, q.z, uy * q.w);
                const float t  = satmul(uv, inv);
                const float dx = fmaf(-t, q.z, ux);
                const float dy = fmaf(-t, q.w, uy);
                m0 = fminf(m0, fmaf(dy, dy, dx * dx));
            }
            {
                const float4 q = s_seg[j + 4]; const float inv = s_inv[j + 4];
                const float ux = gx - q.x, uy = gy - q.y;
                const float uv = fmaf(ux, q.z, uy * q.w);
                const float t  = satmul(uv, inv);
                const float dx = fmaf(-t, q.z, ux);
                const float dy = fmaf(-t, q.w, uy);
                m1 = fminf(m1, fmaf(dy, dy, dx * dx));
            }
        }
        for (; j < cn; j += 4) {
            const float4 q = s_seg[j]; const float inv = s_inv[j];
            const float ux = gx - q.x, uy = gy - q.y;
            const float uv = fmaf(ux, q.z, uy * q.w);
            const float t  = satmul(uv, inv);
            const float dx = fmaf(-t, q.z, ux);
            const float dy = fmaf(-t, q.w, uy);
            m0 = fminf(m0, fmaf(dy, dy, dx * dx));
        }
        __syncthreads();
    }
    s_m[p][h] = fminf(m0, m1);
    __syncthreads();

    // ---------------- Merge slices, publish mins, pair up ----------------
    const int pixbase = (ty * 4) * 128 + tx * 8;   // tile's first pixel
    float qown = 0.0f;
    if (tid < 32) {
        qown = fminf(fminf(s_m[p][0], s_m[p][1]), fminf(s_m[p][2], s_m[p][3]));
        g_pix[w][pixbase + row * 128 + col] = qown;
    }
    __threadfence();
    if (tid == 0) {
        const int old = atomicAdd(&g_tile_cnt[tile], 1);
        s_flag = (old == 1);
    }
    __syncthreads();

    // ---------------- Second arriver: tile loss partial ----------------
    if (s_flag) {
        float v = 0.0f;
        if (tid < 32) {
            const float qoth = g_pix[w ^ 1][pixbase + row * 128 + col];
            const float bo = expf(-GAMMA_F * qown);
            const float bt = expf(-GAMMA_F * qoth);
            const float d  = bo - bt;
            v = d * d;
#pragma unroll
            for (int o = 16; o > 0; o >>= 1)
                v += __shfl_xor_sync(0xFFFFFFFFu, v, o);
        }
        if (tid == 0) {
            atomicAdd(&g_loss, v);
            __threadfence();
            const unsigned old2 = atomicAdd(&g_done, 1u);
            s_flag = (old2 == NTILE - 1) ? 2 : 0;
        }
        __syncthreads();

        // ---------------- Last loss-CTA: finalize + reset ----------------
        if (s_flag == 2) {
            for (int i = tid; i < NTILE; i += 128) g_tile_cnt[i] = 0;
            if (tid == 0) {
                const float total = *((volatile float*)&g_loss);
                out[0] = total * (1.0f / (float)NPIX);
                g_loss = 0.0f;
                g_done = 0u;
            }
        }
    }
}

// ---------------------------------------------------------------------------
extern "C" void kernel_launch(void* const* d_in, const int* in_sizes, int n_in,
                              void* d_out, int out_size) {
    const float* pred = (const float*)d_in[0];
    const float* gt   = (const float*)d_in[1];
    float* out = (float*)d_out;

    fused_kernel<<<1024, 128>>>(pred, gt, out);
}